// round 13
// baseline (speedup 1.0000x reference)
#include <cuda_runtime.h>

// ============================================================================
// MultiHeadAttentionQuantum — algebraic form, fused.
// ev_i = Σ_{a,b} T_i[a][b] m01[a] m23[b]  (81-term multilinear basis in
// {1,cos x_q,sin x_q}); out = W ev + b applied INCREMENTALLY in-register as
// each ev_i is produced (no 16 MB ev scratch, no third kernel).
// Kernel 1 builds T per head (U -> B_i -> separable 3^4 transform).
// Kernel 2: 65536 threads x 2 tokens (f32x2-packed), T rows via LDS.128.
// ============================================================================

#define NQ      4
#define DIM     16
#define NH      8
#define NLAYERS 2
#define EMB     32
#define NTOK    (32 * 4096)
#define NBASIS  81
#define NROWS   (NH * 4 * 9)          // 288 T-rows (h, i, a)
#define ROWW    5                      // ulonglong2 slots per row (9 vals + pad)

typedef unsigned long long ull;

// ---- packed f32x2 helpers (Blackwell sm_103a) ------------------------------
__device__ __forceinline__ ull pk(float lo, float hi) {
    ull r; asm("mov.b64 %0, {%1, %2};" : "=l"(r) : "f"(lo), "f"(hi)); return r;
}
__device__ __forceinline__ void upk(ull v, float& lo, float& hi) {
    asm("mov.b64 {%0, %1}, %2;" : "=f"(lo), "=f"(hi) : "l"(v));
}
__device__ __forceinline__ ull f2mul(ull a, ull b) {
    ull d; asm("mul.rn.f32x2 %0, %1, %2;" : "=l"(d) : "l"(a), "l"(b)); return d;
}
__device__ __forceinline__ ull f2fma(ull a, ull b, ull c) {
    ull d; asm("fma.rn.f32x2 %0, %1, %2, %3;" : "=l"(d) : "l"(a), "l"(b), "l"(c)); return d;
}

// ---- global scratch (static device arrays; no allocation) ------------------
__device__ ulonglong2 g_T2[NROWS * ROWW];      // padded, dup'd T rows

// ============================================================================
// Gate helpers with COMPILE-TIME masks (static register indexing).
// ============================================================================
template<int M>
__device__ __forceinline__ void rot3(float* cr, float* ci, const float* p) {
    float c, s;
    __sincosf(0.5f * p[0], &s, &c);          // RX
#pragma unroll
    for (int j = 0; j < DIM; ++j) if (!(j & M)) {
        const int j1 = j | M;
        float a0r = cr[j],  a0i = ci[j];
        float a1r = cr[j1], a1i = ci[j1];
        cr[j]  = c * a0r + s * a1i;   ci[j]  = c * a0i - s * a1r;
        cr[j1] = c * a1r + s * a0i;   ci[j1] = c * a1i - s * a0r;
    }
    __sincosf(0.5f * p[1], &s, &c);          // RY
#pragma unroll
    for (int j = 0; j < DIM; ++j) if (!(j & M)) {
        const int j1 = j | M;
        float a0r = cr[j],  a0i = ci[j];
        float a1r = cr[j1], a1i = ci[j1];
        cr[j]  = c * a0r - s * a1r;   ci[j]  = c * a0i - s * a1i;
        cr[j1] = s * a0r + c * a1r;   ci[j1] = s * a0i + c * a1i;
    }
    __sincosf(0.5f * p[2], &s, &c);          // RZ
#pragma unroll
    for (int j = 0; j < DIM; ++j) if (!(j & M)) {
        const int j1 = j | M;
        float a0r = cr[j],  a0i = ci[j];
        float a1r = cr[j1], a1i = ci[j1];
        cr[j]  = c * a0r + s * a0i;   ci[j]  = c * a0i - s * a0r;
        cr[j1] = c * a1r - s * a1i;   ci[j1] = c * a1i + s * a1r;
    }
}

template<int CM, int TM>
__device__ __forceinline__ void cnot_g(float* cr, float* ci) {
#pragma unroll
    for (int j = 0; j < DIM; ++j) if ((j & CM) && !(j & TM)) {
        const int j1 = j | TM;
        float tr = cr[j]; cr[j] = cr[j1]; cr[j1] = tr;
        float ti = ci[j]; ci[j] = ci[j1]; ci[j1] = ti;
    }
}

// ============================================================================
// Kernel 1: per head, build U -> B_i -> T via SEPARABLE qubit sweeps.
// One block per head (8 blocks x 128 threads). Params staged via smem so the
// stage-1 sincos chain is not LDG-latency bound.
// ============================================================================
__global__ void precompute_T_kernel(const float* __restrict__ params) {
    __shared__ float sPar[NLAYERS * NQ * 3];
    __shared__ float sUr[DIM * DIM], sUi[DIM * DIM];
    __shared__ float sA[4 * 256];    // ping
    __shared__ float sC[4 * 192];    // pong (max intermediate = 768)
    const int h   = blockIdx.x;
    const int tid = threadIdx.x;

    if (tid < NLAYERS * NQ * 3) sPar[tid] = params[h * NLAYERS * NQ * 3 + tid];
    __syncthreads();

    // ---- stage 1: threads 0..15 each evolve one COLUMN of U ----
    if (tid < DIM) {
        float cr[DIM], ci[DIM];
#pragma unroll
        for (int j = 0; j < DIM; ++j) { cr[j] = (j == tid) ? 1.0f : 0.0f; ci[j] = 0.0f; }
#pragma unroll
        for (int l = 0; l < NLAYERS; ++l) {
            const float* pb = sPar + l * NQ * 3;
            rot3<8>(cr, ci, pb + 0);
            rot3<4>(cr, ci, pb + 3);
            rot3<2>(cr, ci, pb + 6);
            rot3<1>(cr, ci, pb + 9);
            cnot_g<8, 4>(cr, ci);
            cnot_g<4, 2>(cr, ci);
            cnot_g<2, 1>(cr, ci);
            cnot_g<1, 8>(cr, ci);
        }
#pragma unroll
        for (int j = 0; j < DIM; ++j) { sUr[j * DIM + tid] = cr[j]; sUi[j * DIM + tid] = ci[j]; }
    }
    __syncthreads();

    // ---- stage 2: B_i[k][kp] = Σ_j s_ij (Ur_jk Ur_jkp + Ui_jk Ui_jkp) ----
    for (int idx = tid; idx < 4 * 256; idx += 128) {
        const int i  = idx >> 8;
        const int k  = (idx >> 4) & 15;
        const int kp = idx & 15;
        float sum = 0.0f;
#pragma unroll
        for (int j = 0; j < DIM; ++j) {
            float t = sUr[j * DIM + k] * sUr[j * DIM + kp]
                    + sUi[j * DIM + k] * sUi[j * DIM + kp];
            sum += ((j >> (3 - i)) & 1) ? -t : t;
        }
        sA[idx] = sum;
    }
    __syncthreads();

    // ---- stage 3: 4 separable sweeps (qubit q on MSB of remaining bits).
    // out[0]=in(0,0)+in(1,1); out[1]=in(0,0)-in(1,1); out[2]=in(0,1)+in(1,0).
    {
        float* bufs[2] = { sA, sC };
#pragma unroll
        for (int s = 0; s < 4; ++s) {
            const float* in   = bufs[s & 1];
            float*       outb = bufs[(s + 1) & 1];
            const int pow3 = (s == 0) ? 1 : (s == 1) ? 3 : (s == 2) ? 9 : 27;
            const int R    = 4 - s;
            const int half = 1 << (R - 1);
            const int full = 1 << R;
            const int nOut = 4 * pow3 * 3 * half * half;
            for (int o = tid; o < nOut; o += 128) {
                int t = o;
                const int kp_r = t % half;  t /= half;
                const int k_r  = t % half;  t /= half;
                const int mq   = t % 3;     t /= 3;
                const int m    = t % pow3;  t /= pow3;
                const int i    = t;
                const int base = ((i * pow3 + m) * full) * full;
                const int i00 = base + (0 * half + k_r) * full + (0 * half + kp_r);
                const int i11 = base + (1 * half + k_r) * full + (1 * half + kp_r);
                const int i01 = base + (0 * half + k_r) * full + (1 * half + kp_r);
                const int i10 = base + (1 * half + k_r) * full + (0 * half + kp_r);
                float v;
                if (mq == 0)      v = in[i00] + in[i11];
                else if (mq == 1) v = in[i00] - in[i11];
                else              v = in[i01] + in[i10];
                outb[o] = v;
            }
            __syncthreads();
        }
    }
    // final data in sA: (i*81 + m), m = a*9 + b.

    // ---- stage 4: padded dup'd ul2 rows; T = sA / 16 ----
    for (int slot = tid; slot < 4 * 9 * ROWW; slot += 128) {
        const int j = slot % ROWW;
        const int a = (slot / ROWW) % 9;
        const int i = slot / (ROWW * 9);
        const int b0 = 2 * j, b1 = 2 * j + 1;
        const float t0 = sA[i * NBASIS + a * 9 + b0] * 0.0625f;
        const float t1 = (b1 < 9) ? sA[i * NBASIS + a * 9 + b1] * 0.0625f : 0.0f;
        ulonglong2 u; u.x = pk(t0, t0); u.y = pk(t1, t1);
        g_T2[((h * 4 + i) * 9 + a) * ROWW + j] = u;
    }
}

// ============================================================================
// Kernel 2 (FUSED): ev + output projection. 2 tokens/thread (one f32x2 pair),
// 65536 threads. W applied incrementally per ev_i into 32 packed accumulators
// (column-major dup'd W in smem); all register indices compile-time.
// ============================================================================
__global__ __launch_bounds__(128, 4) void fused_kernel(const float* __restrict__ x,
                                                       const float* __restrict__ W,
                                                       const float* __restrict__ bvec,
                                                       float* __restrict__ out) {
    __shared__ ulonglong2 sT2[NROWS * ROWW];   // 22.5 KB
    __shared__ ulonglong2 sWc[EMB * 16];       // 8 KB: [f][ep] = {dup W[2ep][f], dup W[2ep+1][f]}
    __shared__ float      sb[EMB];

    for (int i = threadIdx.x; i < NROWS * ROWW; i += 128) sT2[i] = g_T2[i];
    for (int i = threadIdx.x; i < EMB * 16; i += 128) {
        const int f = i >> 4, ep = i & 15;
        ulonglong2 u;
        const float w0 = W[(2 * ep) * EMB + f], w1 = W[(2 * ep + 1) * EMB + f];
        u.x = pk(w0, w0); u.y = pk(w1, w1);
        sWc[i] = u;
    }
    if (threadIdx.x < EMB) sb[threadIdx.x] = bvec[threadIdx.x];
    __syncthreads();

    const int gid = blockIdx.x * 128 + threadIdx.x;
    const int t0  = gid * 2;

    // 32 packed output accumulators (token t0 in lo, t0+1 in hi)
    ull acc[EMB];
#pragma unroll
    for (int e = 0; e < EMB; ++e) { const float be = sb[e]; acc[e] = pk(be, be); }

#pragma unroll 1
    for (int h = 0; h < NH; ++h) {
        // ---- angles -> packed trig monomials ----
        float4 aa = *reinterpret_cast<const float4*>(x + (size_t)t0 * EMB + h * 4);
        float4 ab = *reinterpret_cast<const float4*>(x + (size_t)(t0 + 1) * EMB + h * 4);
        float c0a, s0a, c0b, s0b, c1a, s1a, c1b, s1b;
        float c2a, s2a, c2b, s2b, c3a, s3a, c3b, s3b;
        __sincosf(aa.x, &s0a, &c0a);  __sincosf(ab.x, &s0b, &c0b);
        __sincosf(aa.y, &s1a, &c1a);  __sincosf(ab.y, &s1b, &c1b);
        __sincosf(aa.z, &s2a, &c2a);  __sincosf(ab.z, &s2b, &c2b);
        __sincosf(aa.w, &s3a, &c3a);  __sincosf(ab.w, &s3b, &c3b);
        const ull C0 = pk(c0a, c0b), S0 = pk(s0a, s0b);
        const ull C1 = pk(c1a, c1b), S1 = pk(s1a, s1b);
        const ull C2 = pk(c2a, c2b), S2 = pk(s2a, s2b);
        const ull C3 = pk(c3a, c3b), S3 = pk(s3a, s3b);
        ull m01[9], m23[9];
        m01[1] = C1;            m01[2] = S1;
        m01[3] = C0;            m01[6] = S0;
        m01[4] = f2mul(C0, C1); m01[5] = f2mul(C0, S1);
        m01[7] = f2mul(S0, C1); m01[8] = f2mul(S0, S1);
        m23[1] = C3;            m23[2] = S3;
        m23[3] = C2;            m23[6] = S2;
        m23[4] = f2mul(C2, C3); m23[5] = f2mul(C2, S3);
        m23[7] = f2mul(S2, C3); m23[8] = f2mul(S2, S3);

#pragma unroll
        for (int i = 0; i < 4; ++i) {
            // ---- ev_i = Σ_a m01[a] (Σ_b T[a][b] m23[b]) ----
            const ulonglong2* Ti = sT2 + ((h * 4 + i) * 9) * ROWW;
            ull evi;
#pragma unroll
            for (int a = 0; a < 9; ++a) {
                const ulonglong2* Tr = Ti + a * ROWW;
                ulonglong2 w = Tr[0];                 // {dup T0, dup T1}
                ull ta = f2fma(w.y, m23[1], w.x);
#pragma unroll
                for (int j = 1; j < 4; ++j) {
                    w = Tr[j];
                    ta = f2fma(w.x, m23[2 * j],     ta);
                    ta = f2fma(w.y, m23[2 * j + 1], ta);
                }
                w = Tr[4];                            // {dup T8, 0}
                ta = f2fma(w.x, m23[8], ta);
                if (a == 0) evi = ta;                 // m01[0] = 1
                else        evi = f2fma(ta, m01[a], evi);
            }
            // ---- incremental output projection: acc[e] += W[e][f] * evi ----
            const ulonglong2* Wf = sWc + (h * 4 + i) * 16;
#pragma unroll
            for (int ep = 0; ep < 16; ++ep) {
                ulonglong2 w = Wf[ep];
                acc[2 * ep]     = f2fma(w.x, evi, acc[2 * ep]);
                acc[2 * ep + 1] = f2fma(w.y, evi, acc[2 * ep + 1]);
            }
        }
    }

    // ---- store both token rows ----
#pragma unroll
    for (int eg = 0; eg < 8; ++eg) {
        float o0[4], o1[4];
#pragma unroll
        for (int r = 0; r < 4; ++r) upk(acc[eg * 4 + r], o0[r], o1[r]);
        *reinterpret_cast<float4*>(out + (size_t)t0 * EMB + eg * 4)       = make_float4(o0[0], o0[1], o0[2], o0[3]);
        *reinterpret_cast<float4*>(out + (size_t)(t0 + 1) * EMB + eg * 4) = make_float4(o1[0], o1[1], o1[2], o1[3]);
    }
}

// ============================================================================
extern "C" void kernel_launch(void* const* d_in, const int* in_sizes, int n_in,
                              void* d_out, int out_size) {
    // Identify inputs by element count (all distinct):
    // x: 4194304, params: 192, W_out: 1024, b_out: 32
    const float* x = 0; const float* params = 0; const float* W = 0; const float* b = 0;
    for (int i = 0; i < n_in; ++i) {
        switch (in_sizes[i]) {
            case 4194304: x      = (const float*)d_in[i]; break;
            case 192:     params = (const float*)d_in[i]; break;
            case 1024:    W      = (const float*)d_in[i]; break;
            case 32:      b      = (const float*)d_in[i]; break;
            default: break;
        }
    }
    float* out = (float*)d_out;

    precompute_T_kernel<<<NH, 128>>>(params);
    fused_kernel<<<512, 128>>>(x, W, b, out);   // 65536 threads * 2 tokens
}